// round 10
// baseline (speedup 1.0000x reference)
#include <cuda_runtime.h>
#include <math.h>

#define NB     8
#define TT     4096
#define HID    4096
#define NSAMP  512
#define NSLOT  16
#define DD     256
#define BOTD   512
#define EPSF   1e-5f

// ---------------- scratch (no allocations allowed) ----------------
__device__ float g_pre    [NB*NSAMP*DD];
__device__ float g_x      [NB*NSAMP*DD];
__device__ float g_k      [NB*NSAMP*DD];
__device__ float g_v      [NB*NSAMP*DD];
__device__ int   g_idx    [NSAMP];
__device__ float g_tpart  [16*NB*HID];
__device__ float g_target [NB*HID];
__device__ float g_slots  [NB*NSLOT*DD];
__device__ float g_s      [NB*NSLOT*DD];
__device__ float g_q      [NB*NSLOT*DD];
__device__ float g_updpart[NB*8*NSLOT*DD];   // (b,chunk,k,d)
__device__ float g_r2     [NB*NSLOT*BOTD];
__device__ float g_rbar   [NB*BOTD];
__device__ float g_recon  [NB*HID];

// ---------------- helpers ----------------
__device__ __forceinline__ float warpSum(float v){
#pragma unroll
    for (int o = 16; o > 0; o >>= 1) v += __shfl_xor_sync(0xffffffffu, v, o);
    return v;
}
__device__ __forceinline__ float geluf(float x){
    return 0.5f * x * (1.0f + erff(x * 0.7071067811865475f));
}

// ---------------- idx = concat(linspace(0,T-256,256).astype(i32), arange(T-256,T)) ----------------
__global__ void k_init_idx(){
    int i = threadIdx.x;
    if (i < 256) {
        const float delta = 3840.0f / 255.0f;     // fp32, matches jnp.linspace step
        g_idx[i] = (int)((float)i * delta);       // truncation == astype(int32)
    } else {
        g_idx[i] = 3840 + (i - 256);
    }
}

// ---------------- target mean: partial sums over 256-step t chunks ----------------
__global__ void __launch_bounds__(256) k_mean_part(const float* __restrict__ hs){
    int hb = blockIdx.x * 1024 + threadIdx.x * 4;
    int b  = blockIdx.y, c = blockIdx.z;
    const float* p = hs + ((size_t)b*TT + (size_t)c*256)*HID + hb;
    float4 acc0 = make_float4(0,0,0,0), acc1 = make_float4(0,0,0,0);
#pragma unroll 4
    for (int t = 0; t < 256; t += 2) {
        float4 v0 = *(const float4*)(p + (size_t)t*HID);
        float4 v1 = *(const float4*)(p + (size_t)(t+1)*HID);
        acc0.x += v0.x; acc0.y += v0.y; acc0.z += v0.z; acc0.w += v0.w;
        acc1.x += v1.x; acc1.y += v1.y; acc1.z += v1.z; acc1.w += v1.w;
    }
    float4 acc = make_float4(acc0.x+acc1.x, acc0.y+acc1.y, acc0.z+acc1.z, acc0.w+acc1.w);
    *(float4*)&g_tpart[((size_t)c*NB + b)*HID + hb] = acc;
}

__global__ void k_mean_reduce(){
    int gi = blockIdx.x * 256 + threadIdx.x;   // gi = b*HID + h, 32768 total
    float s = 0.f;
#pragma unroll
    for (int c = 0; c < 16; c++) s += g_tpart[(size_t)c*NB*HID + gi];
    g_target[gi] = s * (1.0f / (float)TT);
}

// ---------------- SGEMM 64x64x16, 256 thr, 4x4 microtile. N fixed = 256. ----------------
// mode 0: A = gathered hidden rows, B=in_w, C=g_pre (+bias)
// mode 1: A = g_x, B=k_w, C=g_k      mode 2: A = g_x, B=v_w, C=g_v
__global__ void __launch_bounds__(256) k_sgemm(const float* __restrict__ hs,
                                               const float* __restrict__ Bw,
                                               const float* __restrict__ bias,
                                               int Kdim, int mode){
    __shared__ __align__(16) float As[16][64];
    __shared__ __align__(16) float Bs[16][64];
    int tid  = threadIdx.x;
    int brow = blockIdx.y * 64, bcol = blockIdx.x * 64;
    int arow = tid >> 2, ak = (tid & 3) * 4;
    int r    = brow + arow;
    const float* Arow;
    if (mode == 0) {
        int bb = r >> 9; int t = g_idx[r & 511];
        Arow = hs + ((size_t)(bb*TT + t))*HID;
    } else {
        Arow = g_x + (size_t)r * DD;
    }
    float* C = (mode == 0) ? g_pre : (mode == 1 ? g_k : g_v);
    int brr = tid >> 4, bc = (tid & 15) * 4;
    int ty  = tid >> 4, tx = tid & 15;
    float acc[4][4] = {};
    for (int k0 = 0; k0 < Kdim; k0 += 16) {
        float4 a4 = *(const float4*)(Arow + k0 + ak);
        float4 b4 = *(const float4*)(Bw + (size_t)(k0 + brr)*256 + bcol + bc);
        As[ak+0][arow] = a4.x; As[ak+1][arow] = a4.y;
        As[ak+2][arow] = a4.z; As[ak+3][arow] = a4.w;
        *(float4*)&Bs[brr][bc] = b4;
        __syncthreads();
#pragma unroll
        for (int kk = 0; kk < 16; kk++) {
            float4 av = *(const float4*)&As[kk][ty*4];
            float4 bv = *(const float4*)&Bs[kk][tx*4];
            acc[0][0]+=av.x*bv.x; acc[0][1]+=av.x*bv.y; acc[0][2]+=av.x*bv.z; acc[0][3]+=av.x*bv.w;
            acc[1][0]+=av.y*bv.x; acc[1][1]+=av.y*bv.y; acc[1][2]+=av.y*bv.z; acc[1][3]+=av.y*bv.w;
            acc[2][0]+=av.z*bv.x; acc[2][1]+=av.z*bv.y; acc[2][2]+=av.z*bv.z; acc[2][3]+=av.z*bv.w;
            acc[3][0]+=av.w*bv.x; acc[3][1]+=av.w*bv.y; acc[3][2]+=av.w*bv.z; acc[3][3]+=av.w*bv.w;
        }
        __syncthreads();
    }
#pragma unroll
    for (int i = 0; i < 4; i++) {
#pragma unroll
        for (int j = 0; j < 4; j++) {
            int col = bcol + tx*4 + j;
            float bv = bias ? bias[col] : 0.f;
            C[(size_t)(brow + ty*4 + i)*256 + col] = acc[i][j] + bv;
        }
    }
}

// ---------------- LayerNorm of g_pre rows -> g_x ----------------
__global__ void __launch_bounds__(256) k_ln(const float* __restrict__ gg, const float* __restrict__ bb){
    __shared__ float buf[256];
    int r = blockIdx.x, tid = threadIdx.x;
    float v = g_pre[(size_t)r*256 + tid];
    buf[tid] = v; __syncthreads();
    for (int s = 128; s > 0; s >>= 1) { if (tid < s) buf[tid] += buf[tid + s]; __syncthreads(); }
    float mu = buf[0] * (1.f/256.f); __syncthreads();
    float d = v - mu;
    buf[tid] = d * d; __syncthreads();
    for (int s = 128; s > 0; s >>= 1) { if (tid < s) buf[tid] += buf[tid + s]; __syncthreads(); }
    float var = buf[0] * (1.f/256.f);
    g_x[(size_t)r*256 + tid] = d * rsqrtf(var + EPSF) * gg[tid] + bb[tid];
}

// ---------------- slots init ----------------
__global__ void k_copy_in(const float* __restrict__ src){
    int i = blockIdx.x * 256 + threadIdx.x;
    g_slots[i] = src[i];
}

// ---------------- per-iteration: s=LN(slots), q=s@q_w (4 rows per block) ----------------
__global__ void __launch_bounds__(256) k_slotlnq(const float* __restrict__ qw,
                                                 const float* __restrict__ lg,
                                                 const float* __restrict__ lb){
    __shared__ float sm[4][256];
    int tid = threadIdx.x, warp = tid >> 5, lane = tid & 31;
    int b = blockIdx.x >> 2, r0 = (blockIdx.x & 3) * 4;
    if (warp < 4) {
        int row = b*16 + r0 + warp;
        float v[8]; float s1 = 0.f;
#pragma unroll
        for (int j = 0; j < 8; j++) { v[j] = g_slots[(size_t)row*256 + lane + 32*j]; s1 += v[j]; }
        s1 = warpSum(s1); float mu = s1 * (1.f/256.f);
        float s2 = 0.f;
#pragma unroll
        for (int j = 0; j < 8; j++) { float dd = v[j] - mu; s2 += dd*dd; }
        s2 = warpSum(s2); float rs = rsqrtf(s2 * (1.f/256.f) + EPSF);
#pragma unroll
        for (int j = 0; j < 8; j++) {
            int d = lane + 32*j;
            float sv = (v[j] - mu) * rs * lg[d] + lb[d];
            sm[warp][d] = sv;
            g_s[(size_t)row*256 + d] = sv;
        }
    }
    __syncthreads();
    float a0=0,a1=0,a2=0,a3=0;
    for (int d = 0; d < 256; d++) {
        float w = qw[(size_t)d*256 + tid];
        a0 += sm[0][d]*w; a1 += sm[1][d]*w; a2 += sm[2][d]*w; a3 += sm[3][d]*w;
    }
    int base = (b*16 + r0) * 256;
    g_q[base       + tid] = a0;
    g_q[base + 256 + tid] = a1;
    g_q[base + 512 + tid] = a2;
    g_q[base + 768 + tid] = a3;
}

// ---------------- logits + softmax(over slots) + partial upd ----------------
__global__ void __launch_bounds__(256) k_attn(){
    __shared__ __align__(16) float qs[16][260];
    __shared__ __align__(16) float ksh[8][260];
    __shared__ float attn_s[64][16];
    int tid = threadIdx.x;
    int chunk = blockIdx.x, b = blockIdx.y;
#pragma unroll
    for (int i = 0; i < 16; i++) qs[i][tid] = g_q[(size_t)(b*NSLOT + i)*DD + tid];
    __syncthreads();
    int warp = tid >> 5, lane = tid & 31;
    for (int step = 0; step < 8; step++) {
        int nl = step*8 + warp;
        const float* kr = g_k + ((size_t)(b*NSAMP + chunk*64 + nl))*DD;
#pragma unroll
        for (int j = 0; j < 8; j++) ksh[warp][lane + 32*j] = kr[lane + 32*j];
        __syncwarp();
        float logit = -1e30f;
        if (lane < 16) {
            float a = 0.f;
#pragma unroll 8
            for (int d = 0; d < 256; d += 4) {
                float4 qv = *(const float4*)&qs[lane][d];
                float4 kv = *(const float4*)&ksh[warp][d];
                a += qv.x*kv.x + qv.y*kv.y + qv.z*kv.z + qv.w*kv.w;
            }
            logit = a * 0.0625f;           // D^-0.5
        }
        float m = logit;
#pragma unroll
        for (int o = 8; o > 0; o >>= 1) m = fmaxf(m, __shfl_xor_sync(0xffffffffu, m, o));
        float e = expf(logit - m);
        float ss = e;
#pragma unroll
        for (int o = 8; o > 0; o >>= 1) ss += __shfl_xor_sync(0xffffffffu, ss, o);
        if (lane < 16) attn_s[nl][lane] = e / ss;
        __syncwarp();
    }
    __syncthreads();
    float acc[16];
#pragma unroll
    for (int kk = 0; kk < 16; kk++) acc[kk] = 0.f;
    for (int nl = 0; nl < 64; nl++) {
        float vv = g_v[((size_t)(b*NSAMP + chunk*64 + nl))*DD + tid];
#pragma unroll
        for (int kk = 0; kk < 16; kk++) acc[kk] += attn_s[nl][kk] * vv;
    }
#pragma unroll
    for (int kk = 0; kk < 16; kk++)
        g_updpart[((size_t)(b*8 + chunk))*(NSLOT*DD) + kk*DD + tid] = acc[kk];
}

// ---------------- reduce partials + LN + MLP + slot update (4 rows / block) ----------------
__global__ void __launch_bounds__(512) k_updmlp(const float* __restrict__ lmg, const float* __restrict__ lmb,
                                                const float* __restrict__ w1,  const float* __restrict__ b1,
                                                const float* __restrict__ w2,  const float* __restrict__ b2){
    __shared__ float usm[4][256];
    __shared__ float hsm[4][256];
    __shared__ float gsm[4][512];
    int tid = threadIdx.x;
    int b = blockIdx.x >> 2, r0 = (blockIdx.x & 3) * 4;
    for (int idx = tid; idx < 1024; idx += 512) {
        int row = idx >> 8, d = idx & 255;
        float u = 0.f;
#pragma unroll
        for (int c = 0; c < 8; c++)
            u += g_updpart[((size_t)(b*8 + c))*(NSLOT*DD) + (size_t)(r0 + row)*DD + d];
        usm[row][d] = u;
    }
    __syncthreads();
    int warp = tid >> 5, lane = tid & 31;
    if (warp < 4) {
        float v[8]; float s1 = 0.f;
#pragma unroll
        for (int j = 0; j < 8; j++) { v[j] = usm[warp][lane + 32*j]; s1 += v[j]; }
        s1 = warpSum(s1); float mu = s1 * (1.f/256.f);
        float s2 = 0.f;
#pragma unroll
        for (int j = 0; j < 8; j++) { float dd = v[j] - mu; s2 += dd*dd; }
        s2 = warpSum(s2); float rs = rsqrtf(s2 * (1.f/256.f) + EPSF);
#pragma unroll
        for (int j = 0; j < 8; j++) {
            int d = lane + 32*j;
            hsm[warp][d] = (v[j] - mu) * rs * lmg[d] + lmb[d];
        }
    }
    __syncthreads();
    float a0 = b1[tid], a1 = a0, a2 = a0, a3 = a0;
    for (int d = 0; d < 256; d++) {
        float w = w1[(size_t)d*512 + tid];
        a0 += hsm[0][d]*w; a1 += hsm[1][d]*w; a2 += hsm[2][d]*w; a3 += hsm[3][d]*w;
    }
    gsm[0][tid] = geluf(a0); gsm[1][tid] = geluf(a1);
    gsm[2][tid] = geluf(a2); gsm[3][tid] = geluf(a3);
    __syncthreads();
    if (tid < 256) {
        float m0=0,m1=0,m2=0,m3=0;
        for (int j = 0; j < 512; j++) {
            float w = w2[(size_t)j*256 + tid];
            m0 += gsm[0][j]*w; m1 += gsm[1][j]*w; m2 += gsm[2][j]*w; m3 += gsm[3][j]*w;
        }
        float bb = b2[tid];
        int base = (b*16 + r0) * 256;
        g_slots[base       + tid] = g_s[base       + tid] + m0 + bb;
        g_slots[base + 256 + tid] = g_s[base + 256 + tid] + m1 + bb;
        g_slots[base + 512 + tid] = g_s[base + 512 + tid] + m2 + bb;
        g_slots[base + 768 + tid] = g_s[base + 768 + tid] + m3 + bb;
    }
}

// ---------------- decoder stage 1+2 (4 rows / block) ----------------
__global__ void __launch_bounds__(512) k_dec1(const float* __restrict__ w1, const float* __restrict__ b1,
                                              const float* __restrict__ w2, const float* __restrict__ b2){
    __shared__ float ssm[4][256];
    __shared__ float g1[4][512];
    int tid = threadIdx.x;
    int r0 = blockIdx.x * 4;
    for (int idx = tid; idx < 1024; idx += 512)
        ssm[idx >> 8][idx & 255] = g_slots[(size_t)(r0 + (idx >> 8))*256 + (idx & 255)];
    __syncthreads();
    float a0 = b1[tid], a1 = a0, a2 = a0, a3 = a0;
    for (int d = 0; d < 256; d++) {
        float w = w1[(size_t)d*512 + tid];
        a0 += ssm[0][d]*w; a1 += ssm[1][d]*w; a2 += ssm[2][d]*w; a3 += ssm[3][d]*w;
    }
    g1[0][tid] = geluf(a0); g1[1][tid] = geluf(a1);
    g1[2][tid] = geluf(a2); g1[3][tid] = geluf(a3);
    __syncthreads();
    float c0 = b2[tid], c1 = c0, c2 = c0, c3 = c0;
    for (int j = 0; j < 512; j++) {
        float w = w2[(size_t)j*512 + tid];
        c0 += g1[0][j]*w; c1 += g1[1][j]*w; c2 += g1[2][j]*w; c3 += g1[3][j]*w;
    }
    g_r2[(size_t)(r0+0)*512 + tid] = geluf(c0);
    g_r2[(size_t)(r0+1)*512 + tid] = geluf(c1);
    g_r2[(size_t)(r0+2)*512 + tid] = geluf(c2);
    g_r2[(size_t)(r0+3)*512 + tid] = geluf(c3);
}

__global__ void k_rbar(){
    int gi = blockIdx.x * 256 + threadIdx.x;   // 4096 = 8 * 512
    int b = gi >> 9, j = gi & 511;
    float s = 0.f;
#pragma unroll
    for (int kk = 0; kk < 16; kk++) s += g_r2[(size_t)(b*16 + kk)*512 + j];
    g_rbar[gi] = s * (1.f/16.f);
}

__global__ void __launch_bounds__(128) k_recon(const float* __restrict__ w3, const float* __restrict__ b3){
    __shared__ float rb[8][512];
    int tid = threadIdx.x;
    for (int idx = tid; idx < 4096; idx += 128) rb[idx >> 9][idx & 511] = g_rbar[idx];
    __syncthreads();
    int h = blockIdx.x * 128 + tid;
    float bv = b3[h];
    float acc[8];
#pragma unroll
    for (int b = 0; b < 8; b++) acc[b] = bv;
    for (int j = 0; j < 512; j++) {
        float w = w3[(size_t)j*HID + h];
#pragma unroll
        for (int b = 0; b < 8; b++) acc[b] += rb[b][j] * w;
    }
#pragma unroll
    for (int b = 0; b < 8; b++) g_recon[(size_t)b*HID + h] = acc[b];
}

__global__ void __launch_bounds__(1024) k_loss(float* __restrict__ out, int out_size){
    __shared__ float buf[1024];
    int tid = threadIdx.x;
    float s = 0.f;
    for (int i = tid; i < NB*HID; i += 1024) {
        float dd = g_recon[i] - g_target[i];
        s += dd * dd;
    }
    buf[tid] = s; __syncthreads();
    for (int st = 512; st > 0; st >>= 1) { if (tid < st) buf[tid] += buf[tid + st]; __syncthreads(); }
    if (tid == 0) out[out_size - 1] = buf[0] * (1.f / (float)(NB*HID));
}

__global__ void k_copy_out(float* __restrict__ out, int out_size){
    int i = blockIdx.x * 256 + threadIdx.x;
    if (i < NB*NSLOT*DD && i < out_size) out[i] = g_slots[i];
}

// ---------------- launcher ----------------
extern "C" void kernel_launch(void* const* d_in, const int* in_sizes, int n_in,
                              void* d_out, int out_size){
    const float* hs        = (const float*)d_in[0];
    const float* old_slots = (const float*)d_in[1];
    const float* in_w      = (const float*)d_in[2];
    const float* in_b      = (const float*)d_in[3];
    const float* ln_in_g   = (const float*)d_in[4];
    const float* ln_in_b   = (const float*)d_in[5];
    const float* ln_s_g    = (const float*)d_in[6];
    const float* ln_s_b    = (const float*)d_in[7];
    const float* ln_m_g    = (const float*)d_in[8];
    const float* ln_m_b    = (const float*)d_in[9];
    const float* q_w       = (const float*)d_in[10];
    const float* k_w       = (const float*)d_in[11];
    const float* v_w       = (const float*)d_in[12];
    const float* mlp_w1    = (const float*)d_in[13];
    const float* mlp_b1    = (const float*)d_in[14];
    const float* mlp_w2    = (const float*)d_in[15];
    const float* mlp_b2    = (const float*)d_in[16];
    const float* dec_w1    = (const float*)d_in[17];
    const float* dec_b1    = (const float*)d_in[18];
    const float* dec_w2    = (const float*)d_in[19];
    const float* dec_b2    = (const float*)d_in[20];
    const float* dec_w3    = (const float*)d_in[21];
    const float* dec_b3    = (const float*)d_in[22];
    float* out = (float*)d_out;

    k_init_idx<<<1, 512>>>();
    k_mean_part<<<dim3(4, 8, 16), 256>>>(hs);
    k_mean_reduce<<<128, 256>>>();

    k_sgemm<<<dim3(4, 64), 256>>>(hs, in_w, in_b, HID, 0);   // pre = gather(hidden)@in_w + in_b
    k_ln<<<NB*NSAMP, 256>>>(ln_in_g, ln_in_b);               // x = LN(pre)
    k_sgemm<<<dim3(4, 64), 256>>>(hs, k_w, nullptr, DD, 1);  // k = x@k_w
    k_sgemm<<<dim3(4, 64), 256>>>(hs, v_w, nullptr, DD, 2);  // v = x@v_w

    k_copy_in<<<128, 256>>>(old_slots);
    for (int it = 0; it < 3; it++) {
        k_slotlnq<<<32, 256>>>(q_w, ln_s_g, ln_s_b);
        k_attn<<<dim3(8, 8), 256>>>();
        k_updmlp<<<32, 512>>>(ln_m_g, ln_m_b, mlp_w1, mlp_b1, mlp_w2, mlp_b2);
    }

    k_dec1<<<32, 512>>>(dec_w1, dec_b1, dec_w2, dec_b2);
    k_rbar<<<16, 256>>>();
    k_recon<<<32, 128>>>(dec_w3, dec_b3);
    k_loss<<<1, 1024>>>(out, out_size);
    k_copy_out<<<128, 256>>>(out, out_size);
}

// round 11
// speedup vs baseline: 1.0041x; 1.0041x over previous
#include <cuda_runtime.h>
#include <math.h>

#define NB     8
#define TT     4096
#define HID    4096
#define NSAMP  512
#define NSLOT  16
#define DD     256
#define BOTD   512
#define EPSF   1e-5f

// ---------------- scratch (no allocations allowed) ----------------
__device__ float g_pre    [NB*NSAMP*DD];
__device__ float g_x      [NB*NSAMP*DD];
__device__ float g_k      [NB*NSAMP*DD];
__device__ float g_v      [NB*NSAMP*DD];
__device__ int   g_idx    [NSAMP];
__device__ float g_tpart  [16*NB*HID];
__device__ float g_target [NB*HID];
__device__ float g_slots  [NB*NSLOT*DD];
__device__ float g_s      [NB*NSLOT*DD];
__device__ float g_q      [NB*NSLOT*DD];
__device__ float g_updpart[NB*8*NSLOT*DD];   // (b,chunk,k,d)
__device__ float g_r2     [NB*NSLOT*BOTD];
__device__ float g_rbar   [NB*BOTD];
__device__ float g_recon  [NB*HID];

// ---------------- helpers ----------------
__device__ __forceinline__ float warpSum(float v){
#pragma unroll
    for (int o = 16; o > 0; o >>= 1) v += __shfl_xor_sync(0xffffffffu, v, o);
    return v;
}
__device__ __forceinline__ float geluf(float x){
    return 0.5f * x * (1.0f + erff(x * 0.7071067811865475f));
}

// ---------------- idx = concat(linspace(0,T-256,256).astype(i32), arange(T-256,T)) ----------------
__global__ void k_init_idx(){
    int i = threadIdx.x;
    if (i < 256) {
        const float delta = 3840.0f / 255.0f;     // fp32, matches jnp.linspace step
        g_idx[i] = (int)((float)i * delta);       // truncation == astype(int32)
    } else {
        g_idx[i] = 3840 + (i - 256);
    }
}

// ---------------- target mean: partial sums over 256-step t chunks ----------------
__global__ void __launch_bounds__(256) k_mean_part(const float* __restrict__ hs){
    int hb = blockIdx.x * 1024 + threadIdx.x * 4;
    int b  = blockIdx.y, c = blockIdx.z;
    const float* p = hs + ((size_t)b*TT + (size_t)c*256)*HID + hb;
    float4 acc0 = make_float4(0,0,0,0), acc1 = make_float4(0,0,0,0);
#pragma unroll 4
    for (int t = 0; t < 256; t += 2) {
        float4 v0 = *(const float4*)(p + (size_t)t*HID);
        float4 v1 = *(const float4*)(p + (size_t)(t+1)*HID);
        acc0.x += v0.x; acc0.y += v0.y; acc0.z += v0.z; acc0.w += v0.w;
        acc1.x += v1.x; acc1.y += v1.y; acc1.z += v1.z; acc1.w += v1.w;
    }
    float4 acc = make_float4(acc0.x+acc1.x, acc0.y+acc1.y, acc0.z+acc1.z, acc0.w+acc1.w);
    *(float4*)&g_tpart[((size_t)c*NB + b)*HID + hb] = acc;
}

__global__ void k_mean_reduce(){
    int gi = blockIdx.x * 256 + threadIdx.x;   // gi = b*HID + h, 32768 total
    float s = 0.f;
#pragma unroll
    for (int c = 0; c < 16; c++) s += g_tpart[(size_t)c*NB*HID + gi];
    g_target[gi] = s * (1.0f / (float)TT);
}

// ---------------- SGEMM 64x64x16, 256 thr, 4x4 microtile. N fixed = 256. ----------------
// mode 0: A = gathered hidden rows, B=in_w, C=g_pre (+bias)
// mode 1: A = g_x, B=k_w, C=g_k      mode 2: A = g_x, B=v_w, C=g_v
__global__ void __launch_bounds__(256) k_sgemm(const float* __restrict__ hs,
                                               const float* __restrict__ Bw,
                                               const float* __restrict__ bias,
                                               int Kdim, int mode){
    __shared__ __align__(16) float As[16][64];
    __shared__ __align__(16) float Bs[16][64];
    int tid  = threadIdx.x;
    int brow = blockIdx.y * 64, bcol = blockIdx.x * 64;
    int arow = tid >> 2, ak = (tid & 3) * 4;
    int r    = brow + arow;
    const float* Arow;
    if (mode == 0) {
        int bb = r >> 9; int t = g_idx[r & 511];
        Arow = hs + ((size_t)(bb*TT + t))*HID;
    } else {
        Arow = g_x + (size_t)r * DD;
    }
    float* C = (mode == 0) ? g_pre : (mode == 1 ? g_k : g_v);
    int brr = tid >> 4, bc = (tid & 15) * 4;
    int ty  = tid >> 4, tx = tid & 15;
    float acc[4][4] = {};
    for (int k0 = 0; k0 < Kdim; k0 += 16) {
        float4 a4 = *(const float4*)(Arow + k0 + ak);
        float4 b4 = *(const float4*)(Bw + (size_t)(k0 + brr)*256 + bcol + bc);
        As[ak+0][arow] = a4.x; As[ak+1][arow] = a4.y;
        As[ak+2][arow] = a4.z; As[ak+3][arow] = a4.w;
        *(float4*)&Bs[brr][bc] = b4;
        __syncthreads();
#pragma unroll
        for (int kk = 0; kk < 16; kk++) {
            float4 av = *(const float4*)&As[kk][ty*4];
            float4 bv = *(const float4*)&Bs[kk][tx*4];
            acc[0][0]+=av.x*bv.x; acc[0][1]+=av.x*bv.y; acc[0][2]+=av.x*bv.z; acc[0][3]+=av.x*bv.w;
            acc[1][0]+=av.y*bv.x; acc[1][1]+=av.y*bv.y; acc[1][2]+=av.y*bv.z; acc[1][3]+=av.y*bv.w;
            acc[2][0]+=av.z*bv.x; acc[2][1]+=av.z*bv.y; acc[2][2]+=av.z*bv.z; acc[2][3]+=av.z*bv.w;
            acc[3][0]+=av.w*bv.x; acc[3][1]+=av.w*bv.y; acc[3][2]+=av.w*bv.z; acc[3][3]+=av.w*bv.w;
        }
        __syncthreads();
    }
#pragma unroll
    for (int i = 0; i < 4; i++) {
#pragma unroll
        for (int j = 0; j < 4; j++) {
            int col = bcol + tx*4 + j;
            float bv = bias ? bias[col] : 0.f;
            C[(size_t)(brow + ty*4 + i)*256 + col] = acc[i][j] + bv;
        }
    }
}

// ---------------- LayerNorm of g_pre rows -> g_x ----------------
__global__ void __launch_bounds__(256) k_ln(const float* __restrict__ gg, const float* __restrict__ bb){
    __shared__ float buf[256];
    int r = blockIdx.x, tid = threadIdx.x;
    float v = g_pre[(size_t)r*256 + tid];
    buf[tid] = v; __syncthreads();
    for (int s = 128; s > 0; s >>= 1) { if (tid < s) buf[tid] += buf[tid + s]; __syncthreads(); }
    float mu = buf[0] * (1.f/256.f); __syncthreads();
    float d = v - mu;
    buf[tid] = d * d; __syncthreads();
    for (int s = 128; s > 0; s >>= 1) { if (tid < s) buf[tid] += buf[tid + s]; __syncthreads(); }
    float var = buf[0] * (1.f/256.f);
    g_x[(size_t)r*256 + tid] = d * rsqrtf(var + EPSF) * gg[tid] + bb[tid];
}

// ---------------- slots init ----------------
__global__ void k_copy_in(const float* __restrict__ src){
    int i = blockIdx.x * 256 + threadIdx.x;
    g_slots[i] = src[i];
}

// ---------------- per-iteration: s=LN(slots), q=s@q_w (4 rows per block) ----------------
__global__ void __launch_bounds__(256) k_slotlnq(const float* __restrict__ qw,
                                                 const float* __restrict__ lg,
                                                 const float* __restrict__ lb){
    __shared__ float sm[4][256];
    int tid = threadIdx.x, warp = tid >> 5, lane = tid & 31;
    int b = blockIdx.x >> 2, r0 = (blockIdx.x & 3) * 4;
    if (warp < 4) {
        int row = b*16 + r0 + warp;
        float v[8]; float s1 = 0.f;
#pragma unroll
        for (int j = 0; j < 8; j++) { v[j] = g_slots[(size_t)row*256 + lane + 32*j]; s1 += v[j]; }
        s1 = warpSum(s1); float mu = s1 * (1.f/256.f);
        float s2 = 0.f;
#pragma unroll
        for (int j = 0; j < 8; j++) { float dd = v[j] - mu; s2 += dd*dd; }
        s2 = warpSum(s2); float rs = rsqrtf(s2 * (1.f/256.f) + EPSF);
#pragma unroll
        for (int j = 0; j < 8; j++) {
            int d = lane + 32*j;
            float sv = (v[j] - mu) * rs * lg[d] + lb[d];
            sm[warp][d] = sv;
            g_s[(size_t)row*256 + d] = sv;
        }
    }
    __syncthreads();
    float a0=0,a1=0,a2=0,a3=0;
    for (int d = 0; d < 256; d++) {
        float w = qw[(size_t)d*256 + tid];
        a0 += sm[0][d]*w; a1 += sm[1][d]*w; a2 += sm[2][d]*w; a3 += sm[3][d]*w;
    }
    int base = (b*16 + r0) * 256;
    g_q[base       + tid] = a0;
    g_q[base + 256 + tid] = a1;
    g_q[base + 512 + tid] = a2;
    g_q[base + 768 + tid] = a3;
}

// ---------------- logits + softmax(over slots) + partial upd ----------------
__global__ void __launch_bounds__(256) k_attn(){
    __shared__ __align__(16) float qs[16][260];
    __shared__ __align__(16) float ksh[8][260];
    __shared__ float attn_s[64][16];
    int tid = threadIdx.x;
    int chunk = blockIdx.x, b = blockIdx.y;
#pragma unroll
    for (int i = 0; i < 16; i++) qs[i][tid] = g_q[(size_t)(b*NSLOT + i)*DD + tid];
    __syncthreads();
    int warp = tid >> 5, lane = tid & 31;
    for (int step = 0; step < 8; step++) {
        int nl = step*8 + warp;
        const float* kr = g_k + ((size_t)(b*NSAMP + chunk*64 + nl))*DD;
#pragma unroll
        for (int j = 0; j < 8; j++) ksh[warp][lane + 32*j] = kr[lane + 32*j];
        __syncwarp();
        float logit = -1e30f;
        if (lane < 16) {
            float a = 0.f;
#pragma unroll 8
            for (int d = 0; d < 256; d += 4) {
                float4 qv = *(const float4*)&qs[lane][d];
                float4 kv = *(const float4*)&ksh[warp][d];
                a += qv.x*kv.x + qv.y*kv.y + qv.z*kv.z + qv.w*kv.w;
            }
            logit = a * 0.0625f;           // D^-0.5
        }
        float m = logit;
#pragma unroll
        for (int o = 8; o > 0; o >>= 1) m = fmaxf(m, __shfl_xor_sync(0xffffffffu, m, o));
        float e = expf(logit - m);
        float ss = e;
#pragma unroll
        for (int o = 8; o > 0; o >>= 1) ss += __shfl_xor_sync(0xffffffffu, ss, o);
        if (lane < 16) attn_s[nl][lane] = e / ss;
        __syncwarp();
    }
    __syncthreads();
    float acc[16];
#pragma unroll
    for (int kk = 0; kk < 16; kk++) acc[kk] = 0.f;
    for (int nl = 0; nl < 64; nl++) {
        float vv = g_v[((size_t)(b*NSAMP + chunk*64 + nl))*DD + tid];
#pragma unroll
        for (int kk = 0; kk < 16; kk++) acc[kk] += attn_s[nl][kk] * vv;
    }
#pragma unroll
    for (int kk = 0; kk < 16; kk++)
        g_updpart[((size_t)(b*8 + chunk))*(NSLOT*DD) + kk*DD + tid] = acc[kk];
}

// ---------------- reduce partials + LN + MLP + slot update (4 rows / block) ----------------
__global__ void __launch_bounds__(512) k_updmlp(const float* __restrict__ lmg, const float* __restrict__ lmb,
                                                const float* __restrict__ w1,  const float* __restrict__ b1,
                                                const float* __restrict__ w2,  const float* __restrict__ b2){
    __shared__ float usm[4][256];
    __shared__ float hsm[4][256];
    __shared__ float gsm[4][512];
    int tid = threadIdx.x;
    int b = blockIdx.x >> 2, r0 = (blockIdx.x & 3) * 4;
    for (int idx = tid; idx < 1024; idx += 512) {
        int row = idx >> 8, d = idx & 255;
        float u = 0.f;
#pragma unroll
        for (int c = 0; c < 8; c++)
            u += g_updpart[((size_t)(b*8 + c))*(NSLOT*DD) + (size_t)(r0 + row)*DD + d];
        usm[row][d] = u;
    }
    __syncthreads();
    int warp = tid >> 5, lane = tid & 31;
    if (warp < 4) {
        float v[8]; float s1 = 0.f;
#pragma unroll
        for (int j = 0; j < 8; j++) { v[j] = usm[warp][lane + 32*j]; s1 += v[j]; }
        s1 = warpSum(s1); float mu = s1 * (1.f/256.f);
        float s2 = 0.f;
#pragma unroll
        for (int j = 0; j < 8; j++) { float dd = v[j] - mu; s2 += dd*dd; }
        s2 = warpSum(s2); float rs = rsqrtf(s2 * (1.f/256.f) + EPSF);
#pragma unroll
        for (int j = 0; j < 8; j++) {
            int d = lane + 32*j;
            hsm[warp][d] = (v[j] - mu) * rs * lmg[d] + lmb[d];
        }
    }
    __syncthreads();
    float a0 = b1[tid], a1 = a0, a2 = a0, a3 = a0;
    for (int d = 0; d < 256; d++) {
        float w = w1[(size_t)d*512 + tid];
        a0 += hsm[0][d]*w; a1 += hsm[1][d]*w; a2 += hsm[2][d]*w; a3 += hsm[3][d]*w;
    }
    gsm[0][tid] = geluf(a0); gsm[1][tid] = geluf(a1);
    gsm[2][tid] = geluf(a2); gsm[3][tid] = geluf(a3);
    __syncthreads();
    if (tid < 256) {
        float m0=0,m1=0,m2=0,m3=0;
        for (int j = 0; j < 512; j++) {
            float w = w2[(size_t)j*256 + tid];
            m0 += gsm[0][j]*w; m1 += gsm[1][j]*w; m2 += gsm[2][j]*w; m3 += gsm[3][j]*w;
        }
        float bb = b2[tid];
        int base = (b*16 + r0) * 256;
        g_slots[base       + tid] = g_s[base       + tid] + m0 + bb;
        g_slots[base + 256 + tid] = g_s[base + 256 + tid] + m1 + bb;
        g_slots[base + 512 + tid] = g_s[base + 512 + tid] + m2 + bb;
        g_slots[base + 768 + tid] = g_s[base + 768 + tid] + m3 + bb;
    }
}

// ---------------- decoder stage 1+2 (4 rows / block) ----------------
__global__ void __launch_bounds__(512) k_dec1(const float* __restrict__ w1, const float* __restrict__ b1,
                                              const float* __restrict__ w2, const float* __restrict__ b2){
    __shared__ float ssm[4][256];
    __shared__ float g1[4][512];
    int tid = threadIdx.x;
    int r0 = blockIdx.x * 4;
    for (int idx = tid; idx < 1024; idx += 512)
        ssm[idx >> 8][idx & 255] = g_slots[(size_t)(r0 + (idx >> 8))*256 + (idx & 255)];
    __syncthreads();
    float a0 = b1[tid], a1 = a0, a2 = a0, a3 = a0;
    for (int d = 0; d < 256; d++) {
        float w = w1[(size_t)d*512 + tid];
        a0 += ssm[0][d]*w; a1 += ssm[1][d]*w; a2 += ssm[2][d]*w; a3 += ssm[3][d]*w;
    }
    g1[0][tid] = geluf(a0); g1[1][tid] = geluf(a1);
    g1[2][tid] = geluf(a2); g1[3][tid] = geluf(a3);
    __syncthreads();
    float c0 = b2[tid], c1 = c0, c2 = c0, c3 = c0;
    for (int j = 0; j < 512; j++) {
        float w = w2[(size_t)j*512 + tid];
        c0 += g1[0][j]*w; c1 += g1[1][j]*w; c2 += g1[2][j]*w; c3 += g1[3][j]*w;
    }
    g_r2[(size_t)(r0+0)*512 + tid] = geluf(c0);
    g_r2[(size_t)(r0+1)*512 + tid] = geluf(c1);
    g_r2[(size_t)(r0+2)*512 + tid] = geluf(c2);
    g_r2[(size_t)(r0+3)*512 + tid] = geluf(c3);
}

__global__ void k_rbar(){
    int gi = blockIdx.x * 256 + threadIdx.x;   // 4096 = 8 * 512
    int b = gi >> 9, j = gi & 511;
    float s = 0.f;
#pragma unroll
    for (int kk = 0; kk < 16; kk++) s += g_r2[(size_t)(b*16 + kk)*512 + j];
    g_rbar[gi] = s * (1.f/16.f);
}

__global__ void __launch_bounds__(128) k_recon(const float* __restrict__ w3, const float* __restrict__ b3){
    __shared__ float rb[8][512];
    int tid = threadIdx.x;
    for (int idx = tid; idx < 4096; idx += 128) rb[idx >> 9][idx & 511] = g_rbar[idx];
    __syncthreads();
    int h = blockIdx.x * 128 + tid;
    float bv = b3[h];
    float acc[8];
#pragma unroll
    for (int b = 0; b < 8; b++) acc[b] = bv;
    for (int j = 0; j < 512; j++) {
        float w = w3[(size_t)j*HID + h];
#pragma unroll
        for (int b = 0; b < 8; b++) acc[b] += rb[b][j] * w;
    }
#pragma unroll
    for (int b = 0; b < 8; b++) g_recon[(size_t)b*HID + h] = acc[b];
}

__global__ void __launch_bounds__(1024) k_loss(float* __restrict__ out, int out_size){
    __shared__ float buf[1024];
    int tid = threadIdx.x;
    float s = 0.f;
    for (int i = tid; i < NB*HID; i += 1024) {
        float dd = g_recon[i] - g_target[i];
        s += dd * dd;
    }
    buf[tid] = s; __syncthreads();
    for (int st = 512; st > 0; st >>= 1) { if (tid < st) buf[tid] += buf[tid + st]; __syncthreads(); }
    if (tid == 0) out[out_size - 1] = buf[0] * (1.f / (float)(NB*HID));
}

__global__ void k_copy_out(float* __restrict__ out, int out_size){
    int i = blockIdx.x * 256 + threadIdx.x;
    if (i < NB*NSLOT*DD && i < out_size) out[i] = g_slots[i];
}

// ---------------- launcher ----------------
extern "C" void kernel_launch(void* const* d_in, const int* in_sizes, int n_in,
                              void* d_out, int out_size){
    const float* hs        = (const float*)d_in[0];
    const float* old_slots = (const float*)d_in[1];
    const float* in_w      = (const float*)d_in[2];
    const float* in_b      = (const float*)d_in[3];
    const float* ln_in_g   = (const float*)d_in[4];
    const float* ln_in_b   = (const float*)d_in[5];
    const float* ln_s_g    = (const float*)d_in[6];
    const float* ln_s_b    = (const float*)d_in[7];
    const float* ln_m_g    = (const float*)d_in[8];
    const float* ln_m_b    = (const float*)d_in[9];
    const float* q_w       = (const float*)d_in[10];
    const float* k_w       = (const float*)d_in[11];
    const float* v_w       = (const float*)d_in[12];
    const float* mlp_w1    = (const float*)d_in[13];
    const float* mlp_b1    = (const float*)d_in[14];
    const float* mlp_w2    = (const float*)d_in[15];
    const float* mlp_b2    = (const float*)d_in[16];
    const float* dec_w1    = (const float*)d_in[17];
    const float* dec_b1    = (const float*)d_in[18];
    const float* dec_w2    = (const float*)d_in[19];
    const float* dec_b2    = (const float*)d_in[20];
    const float* dec_w3    = (const float*)d_in[21];
    const float* dec_b3    = (const float*)d_in[22];
    float* out = (float*)d_out;

    k_init_idx<<<1, 512>>>();
    k_mean_part<<<dim3(4, 8, 16), 256>>>(hs);
    k_mean_reduce<<<128, 256>>>();

    k_sgemm<<<dim3(4, 64), 256>>>(hs, in_w, in_b, HID, 0);   // pre = gather(hidden)@in_w + in_b
    k_ln<<<NB*NSAMP, 256>>>(ln_in_g, ln_in_b);               // x = LN(pre)
    k_sgemm<<<dim3(4, 64), 256>>>(hs, k_w, nullptr, DD, 1);  // k = x@k_w
    k_sgemm<<<dim3(4, 64), 256>>>(hs, v_w, nullptr, DD, 2);  // v = x@v_w

    k_copy_in<<<128, 256>>>(old_slots);
    for (int it = 0; it < 3; it++) {
        k_slotlnq<<<32, 256>>>(q_w, ln_s_g, ln_s_b);
        k_attn<<<dim3(8, 8), 256>>>();
        k_updmlp<<<32, 512>>>(ln_m_g, ln_m_b, mlp_w1, mlp_b1, mlp_w2, mlp_b2);
    }

    k_dec1<<<32, 512>>>(dec_w1, dec_b1, dec_w2, dec_b2);
    k_rbar<<<16, 256>>>();
    k_recon<<<32, 128>>>(dec_w3, dec_b3);
    k_loss<<<1, 1024>>>(out, out_size);
    k_copy_out<<<128, 256>>>(out, out_size);
}